// round 6
// baseline (speedup 1.0000x reference)
#include <cuda_runtime.h>
#include <cuda_bf16.h>
#include <mma.h>
#include <cstdint>

using namespace nvcuda;

#define NB 16
#define NT_ 2048
#define ND 100
#define NG 2
#define NQ 4
#define NK 1024
#define DG 50
#define CD 50
#define NTOK (NB*NT_)
#define TILE_T 128
#define NTILES (NTOK/TILE_T)
#define KP 208                    // packed K (4x50 split + 3 norm + 5 pad)
#define NCHUNK 64                 // codes per chunk
#define NCH (NK/NCHUNK)           // 16 chunks
#define CHUNK_V (NCHUNK*KP*2/16)  // 16B vectors per chunk copy = 1664

#define OFF_QUANT 0
#define OFF_LOSS  (NTOK*ND)
#define OFF_COMMIT (OFF_LOSS+NTOK)
#define OFF_RECON (OFF_COMMIT+1)

// smem byte offsets
#define RS_B 0
#define QS_B 25600
#define A_B  51200                 // 128 x 208 bf16 = 53248
#define B_B  104448                // 2 x 64 x 208 bf16 = 53248
#define D_B  157696                // 128 x 68 f32 = 34816
#define T2_B 192512                // 256 float4
#define IDX_B 196608               // 128 int
#define SMEM_B 197120

__device__ __nv_bfloat16 g_Bpack[NG*NQ*NK*KP];   // packed codebooks
__device__ float g_cc[NG*NQ*NK];
__device__ float g_commit[NG*NQ];

__device__ __forceinline__ uint32_t smem_u32(const void* p){
    uint32_t a; asm("{ .reg .u64 t; cvta.to.shared.u64 t, %1; cvt.u32.u64 %0, t; }":"=r"(a):"l"(p)); return a;
}
__device__ __forceinline__ void cpasync16(uint32_t dst, const void* src){
    asm volatile("cp.async.cg.shared.global [%0], [%1], 16;"
                 :: "r"(dst), "l"(__cvta_generic_to_global(src)) : "memory");
}
__device__ __forceinline__ void cp_commit(){ asm volatile("cp.async.commit_group;" ::: "memory"); }
template<int N> __device__ __forceinline__ void cp_wait(){ asm volatile("cp.async.wait_group %0;" :: "n"(N) : "memory"); }

// ---- prep: pack codebooks [gq][k][KP] with hi/lo split + norm cols ----
__global__ void prep_kernel(const float* __restrict__ cb){
    int idx = blockIdx.x*256+threadIdx.x;        // 8192 codes
    const float* src = cb + (size_t)idx*CD;
    __nv_bfloat16* dst = g_Bpack + (size_t)idx*KP;
    float cc = 0.f;
    for (int c=0;c<CD;c++){
        float v = src[c]; cc += v*v;
        __nv_bfloat16 h = __float2bfloat16(v);
        __nv_bfloat16 l = __float2bfloat16(v - __bfloat162float(h));
        dst[c] = h; dst[50+c] = l; dst[100+c] = h; dst[150+c] = l;
    }
    __nv_bfloat16 ch = __float2bfloat16(cc);
    float rem = cc - __bfloat162float(ch);
    __nv_bfloat16 cm = __float2bfloat16(rem);
    __nv_bfloat16 cl = __float2bfloat16(rem - __bfloat162float(cm));
    dst[200]=ch; dst[201]=cm; dst[202]=cl;
    for (int c=203;c<KP;c++) dst[c] = __float2bfloat16(0.f);
    g_cc[idx] = cc;
    if (idx < NG*NQ) g_commit[idx] = 0.f;
}

// ---- main: 128 tokens x 1 group per CTA, 256 threads (8 warps) ----
__global__ void __launch_bounds__(256,1)
rvq_main(const float* __restrict__ x, const float* __restrict__ W_in,
         const float* __restrict__ b_in, const float* __restrict__ W_out,
         const float* __restrict__ b_out, const float* __restrict__ cbooks,
         float* __restrict__ out){
    extern __shared__ char smem[];
    float* rS = (float*)(smem+RS_B);
    float* qS = (float*)(smem+QS_B);
    __nv_bfloat16* Ah = (__nv_bfloat16*)(smem+A_B);
    __nv_bfloat16* Bb = (__nv_bfloat16*)(smem+B_B);
    float* Dv = (float*)(smem+D_B);
    float4* t2 = (float4*)(smem+T2_B);
    int* idxS = (int*)(smem+IDX_B);
    const uint32_t sbB = smem_u32(smem) + B_B;

    const int tid = threadIdx.x, wid = tid>>5, lid = tid&31;
    const int g = blockIdx.y, t0 = blockIdx.x*TILE_T;
    const int tok = tid&127, hl = tid>>7;
    const int m0 = wid*16;

    // prologue: project_in (xS/WiS alias A region)
    float* xS = (float*)Ah; float* WiS = (float*)Ah + 6400;
    for (int i=tid;i<TILE_T*DG;i+=256){ int t=i/DG, d=i%DG; xS[i]=x[(size_t)(t0+t)*ND+g*DG+d]; }
    for (int i=tid;i<DG*CD;i+=256) WiS[i]=W_in[g*DG*CD+i];
    __syncthreads();
    {
        float xr[DG];
#pragma unroll 10
        for (int d=0;d<DG;d++) xr[d]=xS[tok*DG+d];
        float rv[25];
        for (int j=0;j<25;j++){ int c=hl*25+j; float s=b_in[g*CD+c];
#pragma unroll 10
            for (int d=0;d<DG;d++) s += xr[d]*WiS[d*CD+c];
            rv[j]=s;
        }
        __syncthreads();                       // xS/WiS reads done
        for (int j=0;j<25;j++){ int c=hl*25+j; rS[tok*CD+c]=rv[j]; qS[tok*CD+c]=0.f; }
        // A constant cols (200..207) once
        if (tid<128){
            Ah[tid*KP+200]=__float2bfloat16(1.f);
            Ah[tid*KP+201]=__float2bfloat16(1.f);
            Ah[tid*KP+202]=__float2bfloat16(1.f);
            for (int c=203;c<KP;c++) Ah[tid*KP+c]=__float2bfloat16(0.f);
        }
    }

    for (int q=0;q<NQ;q++){
        const __nv_bfloat16* Bg = g_Bpack + (size_t)(g*NQ+q)*NK*KP;
        const float* cbg = cbooks + (size_t)(g*NQ+q)*NK*CD;
        const float* ccg = g_cc + (g*NQ+q)*NK;

        __syncthreads();                       // prior-stage A reads / rS writes done
        // A build: -2r split into cols [0,200)
        for (int j=0;j<25;j++){ int c=hl*25+j;
            float v = -2.f*rS[tok*CD+c];
            __nv_bfloat16 h = __float2bfloat16(v);
            __nv_bfloat16 l = __float2bfloat16(v - __bfloat162float(h));
            Ah[tok*KP+c]=h; Ah[tok*KP+50+c]=h; Ah[tok*KP+100+c]=l; Ah[tok*KP+150+c]=l;
        }
        __syncthreads();

        // hoist A fragments for this warp's 16 rows (constant over chunks)
        wmma::fragment<wmma::matrix_a,16,16,16,__nv_bfloat16,wmma::row_major> fa[13];
#pragma unroll
        for (int kf=0;kf<13;kf++)
            wmma::load_matrix_sync(fa[kf], Ah + m0*KP + kf*16, KP);

        // prefetch chunk 0
        for (int i=tid;i<CHUNK_V;i+=256)
            cpasync16(sbB + i*16, (const char*)Bg + i*16);
        cp_commit();

        float v1=__int_as_float(0x7f800000), v2=v1; int i1=0, i2=0;
        for (int nc=0;nc<NCH;nc++){
            int cur = nc&1;
            if (nc<NCH-1){
                const char* src = (const char*)Bg + (size_t)(nc+1)*NCHUNK*KP*2;
                uint32_t db = sbB + ((nc+1)&1)*(NCHUNK*KP*2);
                for (int i=tid;i<CHUNK_V;i+=256) cpasync16(db + i*16, src + i*16);
                cp_commit();
                cp_wait<1>();
            } else cp_wait<0>();
            __syncthreads();                   // B ready; prev scan done

            // wmma: 16 rows x 64 codes
            const __nv_bfloat16* Bc = Bb + cur*(NCHUNK*KP);
            wmma::fragment<wmma::accumulator,16,16,16,float> acc[4];
#pragma unroll
            for (int nf=0;nf<4;nf++) wmma::fill_fragment(acc[nf], 0.f);
#pragma unroll
            for (int kf=0;kf<13;kf++){
#pragma unroll
                for (int nf=0;nf<4;nf++){
                    wmma::fragment<wmma::matrix_b,16,16,16,__nv_bfloat16,wmma::col_major> fb;
                    wmma::load_matrix_sync(fb, Bc + (nf*16)*KP + kf*16, KP);
                    wmma::mma_sync(acc[nf], fa[kf], fb, acc[nf]);
                }
            }
#pragma unroll
            for (int nf=0;nf<4;nf++)
                wmma::store_matrix_sync(Dv + m0*68 + nf*16, acc[nf], 68, wmma::mem_row_major);
            __syncthreads();                   // D visible

            // scan: thread covers (tok, 32 codes)
            const float4* dr = (const float4*)(Dv + tok*68 + hl*32);
#pragma unroll
            for (int j=0;j<8;j++){
                float4 v = dr[j];
                int k0 = nc*NCHUNK + hl*32 + j*4;
                if (v.x < v1){ v2=v1;i2=i1; v1=v.x;i1=k0; } else if (v.x < v2){ v2=v.x;i2=k0; }
                if (v.y < v1){ v2=v1;i2=i1; v1=v.y;i1=k0+1; } else if (v.y < v2){ v2=v.y;i2=k0+1; }
                if (v.z < v1){ v2=v1;i2=i1; v1=v.z;i1=k0+2; } else if (v.z < v2){ v2=v.z;i2=k0+2; }
                if (v.w < v1){ v2=v1;i2=i1; v1=v.w;i1=k0+3; } else if (v.w < v2){ v2=v.w;i2=k0+3; }
            }
        }
        // publish per-(tok,half) top2
        t2[hl*128+tok] = make_float4(v1, __int_as_float(i1), v2, __int_as_float(i2));
        __syncthreads();

        // exact fp32 rescore of 4 candidates (2 per half); thread pair per token
        {
            int tk = tid>>1, sel = tid&1;
            float4 c4 = t2[sel*128+tk];
            int ca = __float_as_int(c4.y), cb2 = __float_as_int(c4.w);
            const float* ra = cbg + (size_t)ca*CD;
            const float* rb = cbg + (size_t)cb2*CD;
            float sa=0.f, sb=0.f;
#pragma unroll 10
            for (int c=0;c<CD;c++){
                float r = rS[tk*CD+c];
                sa = fmaf(r, __ldg(ra+c), sa);
                sb = fmaf(r, __ldg(rb+c), sb);
            }
            float da = fmaf(-2.f, sa, ccg[ca]);
            float db = fmaf(-2.f, sb, ccg[cb2]);
            float dl; int il;
            if (da<db || (da==db && ca<cb2)){ dl=da; il=ca; } else { dl=db; il=cb2; }
            float od = __shfl_xor_sync(0xffffffffu, dl, 1);
            int   oc = __shfl_xor_sync(0xffffffffu, il, 1);
            if (sel==0)
                idxS[tk] = (od<dl || (od==dl && oc<il)) ? oc : il;
        }
        __syncthreads();

        // residual update + qS accumulate + commit loss
        {
            int ii = idxS[tok];
            const float* cr = cbg + (size_t)ii*CD;
            float cl = 0.f;
            for (int j=0;j<25;j++){ int c=hl*25+j;
                float qv = __ldg(cr+c);
                float rr = rS[tok*CD+c];
                float dr2 = qv - rr; cl += dr2*dr2;
                rS[tok*CD+c] = rr - qv;
                qS[tok*CD+c] += qv;
            }
#pragma unroll
            for (int o=16;o;o>>=1) cl += __shfl_down_sync(0xffffffffu, cl, o);
            if (lid==0) atomicAdd(&g_commit[g*NQ+q], cl);
        }
    }

    __syncthreads();
    // project_out (WoS aliases A region)
    float* WoS = (float*)Ah;
    for (int i=tid;i<CD*DG;i+=256) WoS[i]=W_out[g*CD*DG+i];
    __syncthreads();
    for (int j=0;j<25;j++){ int dcol=hl*25+j;
        float s = b_out[g*DG+dcol];
#pragma unroll 10
        for (int c=0;c<CD;c++) s += qS[tok*CD+c]*WoS[c*DG+dcol];
        out[(size_t)(t0+tok)*ND+g*DG+dcol] = s;
    }
}

// ---- finalize: recon/loss/commit ----
__global__ void __launch_bounds__(256)
finalize_kernel(const float* __restrict__ x, float* dst){
    int w = (blockIdx.x*blockDim.x+threadIdx.x)>>5;
    int lane = threadIdx.x&31;
    float cs = 0.f;
#pragma unroll
    for (int i=0;i<NG*NQ;i++) cs += g_commit[i];
    float commit = cs * (1.0f/((float)NTOK*(float)CD*(float)(NG*NQ)));
    if (w < NTOK){
        const float* xr = x + (size_t)w*ND;
        const float* qr = dst + OFF_QUANT + (size_t)w*ND;
        float s = 0.f;
        for (int d=lane;d<ND;d+=32){ float df=xr[d]-qr[d]; s += df*df; }
#pragma unroll
        for (int o=16;o;o>>=1) s += __shfl_down_sync(0xffffffffu, s, o);
        if (lane==0){
            float recon = s*(1.0f/(float)ND);
            dst[OFF_RECON+w] = recon;
            dst[OFF_LOSS+w] = recon + commit;
        }
    }
    if (blockIdx.x==0 && threadIdx.x==0) dst[OFF_COMMIT] = commit;
}

extern "C" void kernel_launch(void* const* d_in, const int* in_sizes, int n_in,
                              void* d_out, int out_size){
    const float* x      = (const float*)d_in[0];
    const float* W_in   = (const float*)d_in[1];
    const float* b_in   = (const float*)d_in[2];
    const float* W_out  = (const float*)d_in[3];
    const float* b_out  = (const float*)d_in[4];
    const float* cbooks = (const float*)d_in[5];
    float* out = (float*)d_out;

    cudaFuncSetAttribute(rvq_main, cudaFuncAttributeMaxDynamicSharedMemorySize, SMEM_B);
    prep_kernel<<<32,256>>>(cbooks);
    rvq_main<<<dim3(NTILES,NG),256,SMEM_B>>>(x, W_in, b_in, W_out, b_out, cbooks, out);
    finalize_kernel<<<(NTOK*32)/256,256>>>(x, out);
}

// round 7
// speedup vs baseline: 2.0409x; 2.0409x over previous
#include <cuda_runtime.h>
#include <cuda_bf16.h>
#include <cstdint>

#define NB 16
#define NT_ 2048
#define ND 100
#define NG 2
#define NQ 4
#define NK 1024
#define DG 50
#define CD 50
#define NTOK (NB*NT_)
#define TILE_T 128
#define NTILES (NTOK/TILE_T)
#define KP 168                     // padded K row stride (elements)
#define NCHUNK 128                 // codes per chunk
#define NCH (NK/NCHUNK)            // 8
#define CHUNK_B (NCHUNK*KP*2)      // 43008 bytes
#define CHUNK_V (CHUNK_B/16)       // 2688 16B vectors

#define OFF_QUANT 0
#define OFF_LOSS  (NTOK*ND)
#define OFF_COMMIT (OFF_LOSS+NTOK)
#define OFF_RECON (OFF_COMMIT+1)

// smem byte offsets
#define RS_B 0                     // 128x50 f32 = 25600
#define QS_B 25600                 // 25600
#define A_B  51200                 // 128x168 bf16 = 43008
#define B_B  94208                 // 2x43008 = 86016
#define T2_B 180224                // 128 int2 = 1024
#define IDX_B 181248               // 128 int
#define SMEM_B 181760

__device__ __nv_bfloat16 g_Bpack[NG*NQ*NK*KP];   // packed codebooks (2.75 MB)
__device__ float g_cc[NG*NQ*NK];
__device__ float g_commit[NG*NQ];

__device__ __forceinline__ uint32_t smem_u32(const void* p){
    uint32_t a; asm("{ .reg .u64 t; cvta.to.shared.u64 t, %1; cvt.u32.u64 %0, t; }":"=r"(a):"l"(p)); return a;
}
__device__ __forceinline__ void cpasync16(uint32_t dst, const void* src){
    asm volatile("cp.async.cg.shared.global [%0], [%1], 16;"
                 :: "r"(dst), "l"(__cvta_generic_to_global(src)) : "memory");
}
__device__ __forceinline__ void cp_commit(){ asm volatile("cp.async.commit_group;" ::: "memory"); }
template<int N> __device__ __forceinline__ void cp_wait(){ asm volatile("cp.async.wait_group %0;" :: "n"(N) : "memory"); }
__device__ __forceinline__ void ldsm_x4(uint32_t (&r)[4], uint32_t addr){
    asm volatile("ldmatrix.sync.aligned.m8n8.x4.shared.b16 {%0,%1,%2,%3}, [%4];"
        : "=r"(r[0]),"=r"(r[1]),"=r"(r[2]),"=r"(r[3]) : "r"(addr));
}
__device__ __forceinline__ void mma16816(float (&d)[4], const uint32_t* a, uint32_t b0, uint32_t b1){
    asm volatile("mma.sync.aligned.m16n8k16.row.col.f32.bf16.bf16.f32 "
        "{%0,%1,%2,%3}, {%4,%5,%6,%7}, {%8,%9}, {%0,%1,%2,%3};"
        : "+f"(d[0]),"+f"(d[1]),"+f"(d[2]),"+f"(d[3])
        : "r"(a[0]),"r"(a[1]),"r"(a[2]),"r"(a[3]), "r"(b0),"r"(b1));
}

// ---- prep: warp per code; pack [bh|bl|bh|norm3|0pad], cc sequential (match R2) ----
__global__ void __launch_bounds__(256) prep_kernel(const float* __restrict__ cb){
    int code = blockIdx.x*8 + (threadIdx.x>>5);          // 8192 codes
    int lane = threadIdx.x&31;
    const float* src = cb + (size_t)code*CD;
    __nv_bfloat16* dst = g_Bpack + (size_t)code*KP;
#pragma unroll
    for (int s=0;s<2;s++){
        int c = lane + s*32;
        if (c < CD){
            float v = src[c];
            __nv_bfloat16 h = __float2bfloat16(v);
            __nv_bfloat16 l = __float2bfloat16(v - __bfloat162float(h));
            dst[c]=h; dst[50+c]=l; dst[100+c]=h;
        }
    }
    if (lane >= 1 && lane <= 15) dst[152+lane] = __float2bfloat16(0.f);  // cols 153..167
    if (lane == 0){
        float cc = 0.f;
        for (int c=0;c<CD;c++){ float v=src[c]; cc += v*v; }   // same order as R2 prep
        __nv_bfloat16 ch = __float2bfloat16(cc);
        float rem = cc - __bfloat162float(ch);
        __nv_bfloat16 cm = __float2bfloat16(rem);
        __nv_bfloat16 cl = __float2bfloat16(rem - __bfloat162float(cm));
        dst[150]=ch; dst[151]=cm; dst[152]=cl;
        g_cc[code] = cc;
        if (code < NG*NQ) g_commit[code] = 0.f;
    }
}

// ---- main: 128 tokens x 1 group per CTA, 256 threads (8 warps) ----
__global__ void __launch_bounds__(256,1)
rvq_main(const float* __restrict__ x, const float* __restrict__ W_in,
         const float* __restrict__ b_in, const float* __restrict__ W_out,
         const float* __restrict__ b_out, const float* __restrict__ cbooks,
         float* __restrict__ out){
    extern __shared__ char smem[];
    float* rS = (float*)(smem+RS_B);
    float* qS = (float*)(smem+QS_B);
    __nv_bfloat16* Ah = (__nv_bfloat16*)(smem+A_B);
    int2* t2S = (int2*)(smem+T2_B);
    int* idxS = (int*)(smem+IDX_B);
    const uint32_t sbA = smem_u32(smem) + A_B;
    const uint32_t sbB = smem_u32(smem) + B_B;

    const int tid = threadIdx.x, wid = tid>>5, lane = tid&31;
    const int g = blockIdx.y, t0 = blockIdx.x*TILE_T;
    const int tok = tid&127, hl = tid>>7;
    const int m0 = wid*16;

    // prologue: project_in (xS/WiS alias A region)
    float* xS = (float*)Ah; float* WiS = (float*)Ah + 6400;
    for (int i=tid;i<TILE_T*DG;i+=256){ int t=i/DG, d=i%DG; xS[i]=x[(size_t)(t0+t)*ND+g*DG+d]; }
    for (int i=tid;i<DG*CD;i+=256) WiS[i]=W_in[g*DG*CD+i];
    __syncthreads();
    {
        float xr[DG];
#pragma unroll 10
        for (int d=0;d<DG;d++) xr[d]=xS[tok*DG+d];
        float rv[25];
        for (int j=0;j<25;j++){ int c=hl*25+j; float s=b_in[g*CD+c];
#pragma unroll 10
            for (int d=0;d<DG;d++) s += xr[d]*WiS[d*CD+c];
            rv[j]=s;
        }
        __syncthreads();                       // xS/WiS reads done; A region free
        for (int j=0;j<25;j++){ int c=hl*25+j; rS[tok*CD+c]=rv[j]; qS[tok*CD+c]=0.f; }
        if (tid < 128){                        // A constant cols per token row
            Ah[tid*KP+150]=__float2bfloat16(1.f);
            Ah[tid*KP+151]=__float2bfloat16(1.f);
            Ah[tid*KP+152]=__float2bfloat16(1.f);
            for (int c=153;c<KP;c++) Ah[tid*KP+c]=__float2bfloat16(0.f);
        }
    }

    const uint32_t aaddr0 = sbA + (uint32_t)(((m0 + (lane&15))*KP + ((lane>>4)<<3))*2);
    const uint32_t bboff  = (uint32_t)((((lane&7)*KP) + (((lane>>3)&3)<<3))*2);

    for (int q=0;q<NQ;q++){
        const __nv_bfloat16* Bg = g_Bpack + (size_t)(g*NQ+q)*NK*KP;
        const float* cbg = cbooks + (size_t)(g*NQ+q)*NK*CD;
        const float* ccg = g_cc + (g*NQ+q)*NK;

        __syncthreads();
        // A build: [-2r hi | -2r hi | -2r lo]
        for (int j=0;j<25;j++){ int c=hl*25+j;
            float v = -2.f*rS[tok*CD+c];
            __nv_bfloat16 h = __float2bfloat16(v);
            __nv_bfloat16 l = __float2bfloat16(v - __bfloat162float(h));
            Ah[tok*KP+c]=h; Ah[tok*KP+50+c]=h; Ah[tok*KP+100+c]=l;
        }
        __syncthreads();

        uint32_t af[10][4];
#pragma unroll
        for (int kf=0;kf<10;kf++) ldsm_x4(af[kf], aaddr0 + kf*32);

        // prefetch chunk 0
        for (int i=tid;i<CHUNK_V;i+=256) cpasync16(sbB + i*16, (const char*)Bg + i*16);
        cp_commit();

        float v1l=__int_as_float(0x7f800000), v2l=v1l, v1h=v1l, v2h=v1l;
        int i1l=0,i2l=0,i1h=0,i2h=0;

        for (int nc=0;nc<NCH;nc++){
            if (nc<NCH-1){
                __syncthreads();               // all warps done consuming buf[(nc+1)&1]
                const char* srcp = (const char*)Bg + (size_t)(nc+1)*CHUNK_B;
                uint32_t db = sbB + ((nc+1)&1)*CHUNK_B;
                for (int i=tid;i<CHUNK_V;i+=256) cpasync16(db + i*16, srcp + i*16);
                cp_commit();
                cp_wait<1>();
            } else cp_wait<0>();
            __syncthreads();                   // chunk nc fully arrived for all threads

            uint32_t bb = sbB + (nc&1)*CHUNK_B + bboff;
#pragma unroll
            for (int nf=0;nf<16;nf++){
                float acc[4] = {0.f,0.f,0.f,0.f};
                uint32_t bn = bb + (uint32_t)(nf*8*KP*2);
#pragma unroll
                for (int kfp=0;kfp<5;kfp++){
                    uint32_t b[4];
                    ldsm_x4(b, bn + kfp*64);
                    mma16816(acc, af[2*kfp],   b[0], b[1]);
                    mma16816(acc, af[2*kfp+1], b[2], b[3]);
                }
                int k0 = nc*NCHUNK + nf*8 + 2*(lane&3);
                if (acc[0] < v1l){ v2l=v1l;i2l=i1l; v1l=acc[0];i1l=k0; } else if (acc[0] < v2l){ v2l=acc[0];i2l=k0; }
                if (acc[1] < v1l){ v2l=v1l;i2l=i1l; v1l=acc[1];i1l=k0+1; } else if (acc[1] < v2l){ v2l=acc[1];i2l=k0+1; }
                if (acc[2] < v1h){ v2h=v1h;i2h=i1h; v1h=acc[2];i1h=k0; } else if (acc[2] < v2h){ v2h=acc[2];i2h=k0; }
                if (acc[3] < v1h){ v2h=v1h;i2h=i1h; v1h=acc[3];i1h=k0+1; } else if (acc[3] < v2h){ v2h=acc[3];i2h=k0+1; }
            }
        }

        // merge top-2 across the 4 lanes of each quad (same token rows)
#pragma unroll
        for (int off=1; off<4; off<<=1){
            float ov1, ov2; int oi1, oi2;
            ov1=__shfl_xor_sync(0xffffffffu,v1l,off); oi1=__shfl_xor_sync(0xffffffffu,i1l,off);
            ov2=__shfl_xor_sync(0xffffffffu,v2l,off); oi2=__shfl_xor_sync(0xffffffffu,i2l,off);
            if (ov1 < v1l || (ov1==v1l && oi1 < i1l)){
                float nv2; int ni2;
                if (v1l < ov2 || (v1l==ov2 && i1l < oi2)){ nv2=v1l; ni2=i1l; } else { nv2=ov2; ni2=oi2; }
                v1l=ov1; i1l=oi1; v2l=nv2; i2l=ni2;
            } else if (ov1 < v2l || (ov1==v2l && oi1 < i2l)){ v2l=ov1; i2l=oi1; }
            ov1=__shfl_xor_sync(0xffffffffu,v1h,off); oi1=__shfl_xor_sync(0xffffffffu,i1h,off);
            ov2=__shfl_xor_sync(0xffffffffu,v2h,off); oi2=__shfl_xor_sync(0xffffffffu,i2h,off);
            if (ov1 < v1h || (ov1==v1h && oi1 < i1h)){
                float nv2; int ni2;
                if (v1h < ov2 || (v1h==ov2 && i1h < oi2)){ nv2=v1h; ni2=i1h; } else { nv2=ov2; ni2=oi2; }
                v1h=ov1; i1h=oi1; v2h=nv2; i2h=ni2;
            } else if (ov1 < v2h || (ov1==v2h && oi1 < i2h)){ v2h=ov1; i2h=oi1; }
        }
        if ((lane&3)==0){
            t2S[m0 + (lane>>2)]     = make_int2(i1l, i2l);
            t2S[m0 + 8 + (lane>>2)] = make_int2(i1h, i2h);
        }
        __syncthreads();

        // exact fp32 rescore of the 2 candidates (thread pair per token)
        {
            int tk = tid>>1, sel = tid&1;
            int2 cd2 = t2S[tk];
            int cand = sel ? cd2.y : cd2.x;
            const float* cr = cbg + (size_t)cand*CD;
            float s = 0.f;
#pragma unroll 10
            for (int c=0;c<CD;c++) s = fmaf(rS[tk*CD+c], __ldg(cr+c), s);
            float d = fmaf(-2.f, s, ccg[cand]);
            float od = __shfl_xor_sync(0xffffffffu, d, 1);
            int   oc = __shfl_xor_sync(0xffffffffu, cand, 1);
            if (sel==0)
                idxS[tk] = (od<d || (od==d && oc<cand)) ? oc : cand;
        }
        __syncthreads();

        // residual update + qS accumulate + commit loss
        {
            int ii = idxS[tok];
            const float* cr = cbg + (size_t)ii*CD;
            float cl = 0.f;
            for (int j=0;j<25;j++){ int c=hl*25+j;
                float qv = __ldg(cr+c);
                float rr = rS[tok*CD+c];
                float dr2 = qv - rr; cl += dr2*dr2;
                rS[tok*CD+c] = rr - qv;
                qS[tok*CD+c] += qv;
            }
#pragma unroll
            for (int o=16;o;o>>=1) cl += __shfl_down_sync(0xffffffffu, cl, o);
            if (lane==0) atomicAdd(&g_commit[g*NQ+q], cl);
        }
    }

    __syncthreads();
    // project_out (WoS aliases A region)
    float* WoS = (float*)Ah;
    for (int i=tid;i<CD*DG;i+=256) WoS[i]=W_out[g*CD*DG+i];
    __syncthreads();
    for (int j=0;j<25;j++){ int dcol=hl*25+j;
        float s = b_out[g*DG+dcol];
#pragma unroll 10
        for (int c=0;c<CD;c++) s += qS[tok*CD+c]*WoS[c*DG+dcol];
        out[(size_t)(t0+tok)*ND+g*DG+dcol] = s;
    }
}

// ---- finalize: recon/loss/commit ----
__global__ void __launch_bounds__(256)
finalize_kernel(const float* __restrict__ x, float* dst){
    int w = (blockIdx.x*blockDim.x+threadIdx.x)>>5;
    int lane = threadIdx.x&31;
    float cs = 0.f;
#pragma unroll
    for (int i=0;i<NG*NQ;i++) cs += g_commit[i];
    float commit = cs * (1.0f/((float)NTOK*(float)CD*(float)(NG*NQ)));
    if (w < NTOK){
        const float* xr = x + (size_t)w*ND;
        const float* qr = dst + OFF_QUANT + (size_t)w*ND;
        float s = 0.f;
        for (int d=lane;d<ND;d+=32){ float df=xr[d]-qr[d]; s += df*df; }
#pragma unroll
        for (int o=16;o;o>>=1) s += __shfl_down_sync(0xffffffffu, s, o);
        if (lane==0){
            float recon = s*(1.0f/(float)ND);
            dst[OFF_RECON+w] = recon;
            dst[OFF_LOSS+w] = recon + commit;
        }
    }
    if (blockIdx.x==0 && threadIdx.x==0) dst[OFF_COMMIT] = commit;
}

extern "C" void kernel_launch(void* const* d_in, const int* in_sizes, int n_in,
                              void* d_out, int out_size){
    const float* x      = (const float*)d_in[0];
    const float* W_in   = (const float*)d_in[1];
    const float* b_in   = (const float*)d_in[2];
    const float* W_out  = (const float*)d_in[3];
    const float* b_out  = (const float*)d_in[4];
    const float* cbooks = (const float*)d_in[5];
    float* out = (float*)d_out;

    cudaFuncSetAttribute(rvq_main, cudaFuncAttributeMaxDynamicSharedMemorySize, SMEM_B);
    prep_kernel<<<1024,256>>>(cbooks);
    rvq_main<<<dim3(NTILES,NG),256,SMEM_B>>>(x, W_in, b_in, W_out, b_out, cbooks, out);
    finalize_kernel<<<(NTOK*32)/256,256>>>(x, out);
}